// round 13
// baseline (speedup 1.0000x reference)
#include <cuda_runtime.h>
#include <cstdint>

#define NODES 100000
#define EDGES 1600000
#define HCAT  64

// ---------------- static scratch (no runtime allocation allowed) ------------
__device__ float g_xlin1[(size_t)NODES * HCAT];
__device__ float g_xres1[(size_t)NODES * HCAT];
__device__ float g_hbuf [(size_t)NODES * HCAT];
__device__ float g_xlin2[(size_t)NODES * HCAT];
__device__ float g_al1[NODES * 4];
__device__ float g_ar1[NODES * 4];
__device__ float g_al2[NODES];
__device__ float g_ar2[NODES];
__device__ int   g_deg [NODES];          // zero at load; scan re-zeroes each call
__device__ int   g_offs[NODES + 1];
__device__ int   g_cur [NODES];
__device__ int   g_csr [EDGES];

// ---------------- packed f32x2 + async-copy helpers ---------------------------
typedef unsigned long long ull;

__device__ __forceinline__ ull fma2(ull a, ull b, ull c) {
    ull d;
    asm("fma.rn.f32x2 %0, %1, %2, %3;" : "=l"(d) : "l"(a), "l"(b), "l"(c));
    return d;
}
__device__ __forceinline__ ull pack2(float x) {
    ull r;
    asm("mov.b64 %0, {%1, %1};" : "=l"(r) : "f"(x));
    return r;
}
__device__ __forceinline__ float2 unpack2(ull v) {
    float2 r;
    asm("mov.b64 {%0, %1}, %2;" : "=f"(r.x), "=f"(r.y) : "l"(v));
    return r;
}
__device__ __forceinline__ void cp16(unsigned int smem_addr, const void* gptr) {
    asm volatile("cp.async.ca.shared.global [%0], [%1], 16;"
                 :: "r"(smem_addr), "l"(gptr));
}
__device__ __forceinline__ void cp_commit() { asm volatile("cp.async.commit_group;"); }
__device__ __forceinline__ void cp_wait0()  { asm volatile("cp.async.wait_group 0;"); }

// ---------------- CSR build --------------------------------------------------
__global__ void hist_kernel(const int* __restrict__ dst, int* __restrict__ deg) {
    int i = blockIdx.x * blockDim.x + threadIdx.x;
    if (i < EDGES) atomicAdd(&deg[dst[i]], 1);
}

// scan consumes deg and re-zeroes it (restores the load-time invariant)
__global__ void scan_kernel(int* __restrict__ deg, int* __restrict__ offs,
                            int* __restrict__ cur) {
    __shared__ int sums[1024];
    int t = threadIdx.x;
    const int CH = (NODES + 1023) / 1024;
    int b = t * CH;
    int e = (b + CH < NODES) ? (b + CH) : NODES;
    int s = 0;
    for (int i = b; i < e; i++) s += deg[i];
    sums[t] = s;
    __syncthreads();
    for (int off = 1; off < 1024; off <<= 1) {
        int v = (t >= off) ? sums[t - off] : 0;
        __syncthreads();
        sums[t] += v;
        __syncthreads();
    }
    int run = sums[t] - s;
    for (int i = b; i < e; i++) {
        int d = deg[i];
        deg[i] = 0;
        offs[i] = run;
        cur[i]  = run;
        run += d;
    }
    if (t == 1023) offs[NODES] = sums[1023];
}

__global__ void scatter_kernel(const int* __restrict__ src, const int* __restrict__ dst,
                               int* __restrict__ cur, int* __restrict__ csr) {
    int i = blockIdx.x * blockDim.x + threadIdx.x;
    if (i < EDGES) {
        int p = atomicAdd(&cur[dst[i]], 1);
        csr[p] = src[i];
    }
}

// ---------------- fused layer-1 GEMM: X@[W1|Wres], double-buffered -----------
__global__ void __launch_bounds__(256)
gemm1_kernel(const float* __restrict__ X, const float* __restrict__ W1,
             const float* __restrict__ Wres, const float* __restrict__ attl,
             const float* __restrict__ attr,
             float* __restrict__ xlin, float* __restrict__ xres,
             float* __restrict__ al, float* __restrict__ ar) {
    __shared__ float xs[2][32 * 68];    // [buf][k][row], stride 68
    __shared__ float ws[2][32 * 128];   // [buf][k][col 0:64=W1 | 64:128=Wres]
    const int tid  = threadIdx.x;
    const int cg   = tid & 15;
    const int rg   = tid >> 4;
    const int row0 = blockIdx.x * 64;

    const int lrow0 = (tid * 4) >> 5,          lkk0 = (tid * 4) & 31;
    const int lrow1 = (tid * 4 + 1024) >> 5,   lkk1 = (tid * 4 + 1024) & 31;
    const int gr0 = row0 + lrow0, gr1 = row0 + lrow1;
    const float* xp0 = X + (size_t)gr0 * 128 + lkk0;
    const float* xp1 = X + (size_t)gr1 * 128 + lkk1;

    ull accA[4][2], accB[4][2];
#pragma unroll
    for (int r = 0; r < 4; r++) {
        accA[r][0] = accA[r][1] = 0ull;
        accB[r][0] = accB[r][1] = 0ull;
    }

    auto issueW = [&](int k0, int buf) {
#pragma unroll
        for (int i = 0; i < 4; i++) {
            int flat = tid * 4 + i * 1024;
            int k    = flat >> 7;
            int c    = flat & 127;
            const float* src = (c < 64)
                ? (W1   + (size_t)(k0 + k) * 64 + c)
                : (Wres + (size_t)(k0 + k) * 64 + (c - 64));
            cp16((unsigned int)__cvta_generic_to_shared(&ws[buf][k * 128 + c]), src);
        }
        cp_commit();
    };
    auto loadX = [&](int k0, float4& v0, float4& v1) {
        v0 = make_float4(0.f, 0.f, 0.f, 0.f);
        v1 = make_float4(0.f, 0.f, 0.f, 0.f);
        if (gr0 < NODES) v0 = *(const float4*)(xp0 + k0);
        if (gr1 < NODES) v1 = *(const float4*)(xp1 + k0);
    };
    auto storeX = [&](int buf, const float4& v0, const float4& v1) {
        xs[buf][(lkk0 + 0) * 68 + lrow0] = v0.x;
        xs[buf][(lkk0 + 1) * 68 + lrow0] = v0.y;
        xs[buf][(lkk0 + 2) * 68 + lrow0] = v0.z;
        xs[buf][(lkk0 + 3) * 68 + lrow0] = v0.w;
        xs[buf][(lkk1 + 0) * 68 + lrow1] = v1.x;
        xs[buf][(lkk1 + 1) * 68 + lrow1] = v1.y;
        xs[buf][(lkk1 + 2) * 68 + lrow1] = v1.z;
        xs[buf][(lkk1 + 3) * 68 + lrow1] = v1.w;
    };

    {
        float4 v0, v1;
        loadX(0, v0, v1);
        issueW(0, 0);
        storeX(0, v0, v1);
        cp_wait0();
    }
    __syncthreads();

    int buf = 0;
    for (int k0 = 0; k0 < 128; k0 += 32) {
        const int nk = k0 + 32;
        float4 v0, v1;
        if (nk < 128) {
            loadX(nk, v0, v1);
            issueW(nk, buf ^ 1);
        }
        const float* xb = xs[buf];
        const float* wb = ws[buf];
#pragma unroll 8
        for (int k = 0; k < 32; k++) {
            float4 xv = *(const float4*)(&xb[k * 68 + rg * 4]);
            const float* wrow = &wb[k * 128];
            ulonglong2 wA = *(const ulonglong2*)(wrow + cg * 4);
            ulonglong2 wB = *(const ulonglong2*)(wrow + 64 + cg * 4);
            ull px0 = pack2(xv.x), px1 = pack2(xv.y);
            ull px2 = pack2(xv.z), px3 = pack2(xv.w);
            accA[0][0] = fma2(px0, wA.x, accA[0][0]);
            accA[0][1] = fma2(px0, wA.y, accA[0][1]);
            accB[0][0] = fma2(px0, wB.x, accB[0][0]);
            accB[0][1] = fma2(px0, wB.y, accB[0][1]);
            accA[1][0] = fma2(px1, wA.x, accA[1][0]);
            accA[1][1] = fma2(px1, wA.y, accA[1][1]);
            accB[1][0] = fma2(px1, wB.x, accB[1][0]);
            accB[1][1] = fma2(px1, wB.y, accB[1][1]);
            accA[2][0] = fma2(px2, wA.x, accA[2][0]);
            accA[2][1] = fma2(px2, wA.y, accA[2][1]);
            accB[2][0] = fma2(px2, wB.x, accB[2][0]);
            accB[2][1] = fma2(px2, wB.y, accB[2][1]);
            accA[3][0] = fma2(px3, wA.x, accA[3][0]);
            accA[3][1] = fma2(px3, wA.y, accA[3][1]);
            accB[3][0] = fma2(px3, wB.x, accB[3][0]);
            accB[3][1] = fma2(px3, wB.y, accB[3][1]);
        }
        if (nk < 128) {
            storeX(buf ^ 1, v0, v1);
            cp_wait0();
            __syncthreads();
            buf ^= 1;
        }
    }

    float4 la = *(const float4*)(attl + cg * 4);
    float4 ra = *(const float4*)(attr + cg * 4);
    const int h = cg >> 2;

#pragma unroll
    for (int r = 0; r < 4; r++) {
        int gr = row0 + rg * 4 + r;
        float2 a0 = unpack2(accA[r][0]), a1 = unpack2(accA[r][1]);
        float2 b0 = unpack2(accB[r][0]), b1 = unpack2(accB[r][1]);
        float4 fa = make_float4(a0.x, a0.y, a1.x, a1.y);
        float4 fb = make_float4(b0.x, b0.y, b1.x, b1.y);
        if (gr < NODES) {
            *(float4*)(xlin + (size_t)gr * 64 + cg * 4) = fa;
            *(float4*)(xres + (size_t)gr * 64 + cg * 4) = fb;
        }
        float pl = fa.x * la.x + fa.y * la.y + fa.z * la.z + fa.w * la.w;
        float pr = fa.x * ra.x + fa.y * ra.y + fa.z * ra.z + fa.w * ra.w;
        pl += __shfl_xor_sync(0xffffffffu, pl, 1);
        pl += __shfl_xor_sync(0xffffffffu, pl, 2);
        pr += __shfl_xor_sync(0xffffffffu, pr, 1);
        pr += __shfl_xor_sync(0xffffffffu, pr, 2);
        if ((cg & 3) == 0 && gr < NODES) {
            al[(size_t)gr * 4 + h] = pl;
            ar[(size_t)gr * 4 + h] = pr;
        }
    }
}

// ---------------- layer-2 GEMM: H@W2 (64x64), double-buffered ----------------
__global__ void __launch_bounds__(256)
gemm2_kernel(const float* __restrict__ X, const float* __restrict__ W,
             const float* __restrict__ attl, const float* __restrict__ attr,
             float* __restrict__ xlin, float* __restrict__ al,
             float* __restrict__ ar) {
    __shared__ float xs[2][32 * 68];
    __shared__ float ws[2][32 * 64];
    const int tid  = threadIdx.x;
    const int cg   = tid & 15;
    const int rg   = tid >> 4;
    const int row0 = blockIdx.x * 64;

    const int lrow0 = (tid * 4) >> 5,          lkk0 = (tid * 4) & 31;
    const int lrow1 = (tid * 4 + 1024) >> 5,   lkk1 = (tid * 4 + 1024) & 31;
    const int gr0 = row0 + lrow0, gr1 = row0 + lrow1;
    const float* xp0 = X + (size_t)gr0 * 64 + lkk0;
    const float* xp1 = X + (size_t)gr1 * 64 + lkk1;

    ull acc[4][2];
#pragma unroll
    for (int r = 0; r < 4; r++) acc[r][0] = acc[r][1] = 0ull;

    auto issueW = [&](int k0, int buf) {
#pragma unroll
        for (int i = 0; i < 2; i++) {
            int flat = tid * 4 + i * 1024;
            int k    = flat >> 6;
            int c    = flat & 63;
            cp16((unsigned int)__cvta_generic_to_shared(&ws[buf][k * 64 + c]),
                 W + (size_t)(k0 + k) * 64 + c);
        }
        cp_commit();
    };
    auto loadX = [&](int k0, float4& v0, float4& v1) {
        v0 = make_float4(0.f, 0.f, 0.f, 0.f);
        v1 = make_float4(0.f, 0.f, 0.f, 0.f);
        if (gr0 < NODES) v0 = *(const float4*)(xp0 + k0);
        if (gr1 < NODES) v1 = *(const float4*)(xp1 + k0);
    };
    auto storeX = [&](int buf, const float4& v0, const float4& v1) {
        xs[buf][(lkk0 + 0) * 68 + lrow0] = v0.x;
        xs[buf][(lkk0 + 1) * 68 + lrow0] = v0.y;
        xs[buf][(lkk0 + 2) * 68 + lrow0] = v0.z;
        xs[buf][(lkk0 + 3) * 68 + lrow0] = v0.w;
        xs[buf][(lkk1 + 0) * 68 + lrow1] = v1.x;
        xs[buf][(lkk1 + 1) * 68 + lrow1] = v1.y;
        xs[buf][(lkk1 + 2) * 68 + lrow1] = v1.z;
        xs[buf][(lkk1 + 3) * 68 + lrow1] = v1.w;
    };

    {
        float4 v0, v1;
        loadX(0, v0, v1);
        issueW(0, 0);
        storeX(0, v0, v1);
        cp_wait0();
    }
    __syncthreads();

    int buf = 0;
    for (int k0 = 0; k0 < 64; k0 += 32) {
        const int nk = k0 + 32;
        float4 v0, v1;
        if (nk < 64) {
            loadX(nk, v0, v1);
            issueW(nk, buf ^ 1);
        }
        const float* xb = xs[buf];
        const float* wb = ws[buf];
#pragma unroll 8
        for (int k = 0; k < 32; k++) {
            float4 xv = *(const float4*)(&xb[k * 68 + rg * 4]);
            const float* wrow = &wb[k * 64];
            ulonglong2 w01 = *(const ulonglong2*)(wrow + cg * 4);
            ull px0 = pack2(xv.x), px1 = pack2(xv.y);
            ull px2 = pack2(xv.z), px3 = pack2(xv.w);
            acc[0][0] = fma2(px0, w01.x, acc[0][0]);
            acc[0][1] = fma2(px0, w01.y, acc[0][1]);
            acc[1][0] = fma2(px1, w01.x, acc[1][0]);
            acc[1][1] = fma2(px1, w01.y, acc[1][1]);
            acc[2][0] = fma2(px2, w01.x, acc[2][0]);
            acc[2][1] = fma2(px2, w01.y, acc[2][1]);
            acc[3][0] = fma2(px3, w01.x, acc[3][0]);
            acc[3][1] = fma2(px3, w01.y, acc[3][1]);
        }
        if (nk < 64) {
            storeX(buf ^ 1, v0, v1);
            cp_wait0();
            __syncthreads();
            buf ^= 1;
        }
    }

    float4 la = *(const float4*)(attl + cg * 4);
    float4 ra = *(const float4*)(attr + cg * 4);

#pragma unroll
    for (int r = 0; r < 4; r++) {
        int gr = row0 + rg * 4 + r;
        float2 a0 = unpack2(acc[r][0]), a1 = unpack2(acc[r][1]);
        float4 fa = make_float4(a0.x, a0.y, a1.x, a1.y);
        if (gr < NODES)
            *(float4*)(xlin + (size_t)gr * 64 + cg * 4) = fa;
        float pl = fa.x * la.x + fa.y * la.y + fa.z * la.z + fa.w * la.w;
        float pr = fa.x * ra.x + fa.y * ra.y + fa.z * ra.z + fa.w * ra.w;
#pragma unroll
        for (int o = 1; o <= 8; o <<= 1) {
            pl += __shfl_xor_sync(0xffffffffu, pl, o);
            pr += __shfl_xor_sync(0xffffffffu, pr, o);
        }
        if (cg == 0 && gr < NODES) {
            al[gr] = pl;
            ar[gr] = pr;
        }
    }
}

// ---------------- fused softmax-attention aggregation (no max pass) ----------
template <int H, int C, bool ELU>
__global__ void __launch_bounds__(256)
agg_kernel(const int* __restrict__ offs, const int* __restrict__ csr,
           const float* __restrict__ xlin, const float* __restrict__ al,
           const float* __restrict__ ar, const float* __restrict__ xres,
           const float* __restrict__ bias, float* __restrict__ out) {
    int w = (blockIdx.x * blockDim.x + threadIdx.x) >> 5;
    if (w >= NODES) return;
    const int lane = threadIdx.x & 31;
    const int hl   = lane & 15;
    const int half = lane >> 4;
    const int myh  = (4 * hl) / C;
    const int o0 = offs[w];
    const int o1 = offs[w + 1];

    const float ar_my = ar[w * H + myh];
    const float4* __restrict__ xl4 = (const float4*)xlin + hl;
    const float*  __restrict__ alh = al + myh;

    float4 acc = make_float4(0.f, 0.f, 0.f, 0.f);
    float  ssum = 0.f;
    for (int i = o0 + half; i < o1; i += 2) {
        int s = csr[i];
        float v = alh[s * H] + ar_my;
        v = v > 0.f ? v : 0.2f * v;
        float e = __expf(v);
        ssum += e;
        float4 xv = xl4[s * 16];
        acc.x += e * xv.x; acc.y += e * xv.y; acc.z += e * xv.z; acc.w += e * xv.w;
    }
    acc.x += __shfl_xor_sync(0xffffffffu, acc.x, 16);
    acc.y += __shfl_xor_sync(0xffffffffu, acc.y, 16);
    acc.z += __shfl_xor_sync(0xffffffffu, acc.z, 16);
    acc.w += __shfl_xor_sync(0xffffffffu, acc.w, 16);
    ssum  += __shfl_xor_sync(0xffffffffu, ssum, 16);

    if (half == 0) {
        float inv = 1.f / (ssum + 1e-16f);
        float4 rv = ((const float4*)xres)[w * 16 + hl];
        float4 bv = ((const float4*)bias)[hl];
        float4 r;
        r.x = acc.x * inv + rv.x + bv.x;
        r.y = acc.y * inv + rv.y + bv.y;
        r.z = acc.z * inv + rv.z + bv.z;
        r.w = acc.w * inv + rv.w + bv.w;
        if (ELU) {
            r.x = r.x > 0.f ? r.x : __expf(r.x) - 1.f;
            r.y = r.y > 0.f ? r.y : __expf(r.y) - 1.f;
            r.z = r.z > 0.f ? r.z : __expf(r.z) - 1.f;
            r.w = r.w > 0.f ? r.w : __expf(r.w) - 1.f;
        }
        ((float4*)out)[w * 16 + hl] = r;
    }
}

// ---------------- launch: fork-join overlap of gemm1 with CSR build ----------
extern "C" void kernel_launch(void* const* d_in, const int* in_sizes, int n_in,
                              void* d_out, int out_size) {
    const float* x     = (const float*)d_in[0];
    const int*   ei    = (const int*)d_in[1];
    const float* W1    = (const float*)d_in[2];
    const float* attl1 = (const float*)d_in[3];
    const float* attr1 = (const float*)d_in[4];
    const float* resW1 = (const float*)d_in[5];
    const float* b1    = (const float*)d_in[6];
    const float* W2    = (const float*)d_in[7];
    const float* attl2 = (const float*)d_in[8];
    const float* attr2 = (const float*)d_in[9];
    const float* b2    = (const float*)d_in[10];
    float* out = (float*)d_out;
    const int* src = ei;
    const int* dst = ei + EDGES;

    float *xlin1, *xres1, *hbuf, *xlin2, *al1, *ar1, *al2, *ar2;
    int *deg, *offs, *cur, *csr;
    cudaGetSymbolAddress((void**)&xlin1, g_xlin1);
    cudaGetSymbolAddress((void**)&xres1, g_xres1);
    cudaGetSymbolAddress((void**)&hbuf,  g_hbuf);
    cudaGetSymbolAddress((void**)&xlin2, g_xlin2);
    cudaGetSymbolAddress((void**)&al1,   g_al1);
    cudaGetSymbolAddress((void**)&ar1,   g_ar1);
    cudaGetSymbolAddress((void**)&al2,   g_al2);
    cudaGetSymbolAddress((void**)&ar2,   g_ar2);
    cudaGetSymbolAddress((void**)&deg,   g_deg);
    cudaGetSymbolAddress((void**)&offs,  g_offs);
    cudaGetSymbolAddress((void**)&cur,   g_cur);
    cudaGetSymbolAddress((void**)&csr,   g_csr);

    const int TB = 256;
    const int GB = (NODES + 63) / 64;
    const int WG = (NODES * 32 + TB - 1) / TB;   // warp per node
    const int HB = (EDGES + TB - 1) / TB;

    // Fork-join: gemm1 (FMA-bound) overlaps the CSR chain (atomic/L2-bound).
    // Stream/events created per call; NOT destroyed (destroying a stream that
    // participated in an active capture invalidates it). Host-side only.
    cudaStream_t s2;
    cudaStreamCreateWithFlags(&s2, cudaStreamNonBlocking);
    cudaEvent_t eFork, eJoin;
    cudaEventCreateWithFlags(&eFork, cudaEventDisableTiming);
    cudaEventCreateWithFlags(&eJoin, cudaEventDisableTiming);

    cudaEventRecord(eFork, 0);
    // main stream: CSR chain (deg==0 invariant held by scan's re-zero)
    hist_kernel<<<HB, TB>>>(dst, deg);
    scan_kernel<<<1, 1024>>>(deg, offs, cur);
    scatter_kernel<<<HB, TB>>>(src, dst, cur, csr);
    // side stream: gemm1, concurrent with the chain above
    cudaStreamWaitEvent(s2, eFork, 0);
    gemm1_kernel<<<GB, 256, 0, s2>>>(x, W1, resW1, attl1, attr1,
                                     xlin1, xres1, al1, ar1);
    cudaEventRecord(eJoin, s2);
    cudaStreamWaitEvent(0, eJoin, 0);

    agg_kernel<4, 16, true><<<WG, TB>>>(offs, csr, xlin1, al1, ar1, xres1, b1, hbuf);
    gemm2_kernel<<<GB, 256>>>(hbuf, W2, attl2, attr2, xlin2, al2, ar2);
    agg_kernel<1, 64, false><<<WG, TB>>>(offs, csr, xlin2, al2, ar2, xlin2, b2, out);
}

// round 15
// speedup vs baseline: 2.0377x; 2.0377x over previous
#include <cuda_runtime.h>
#include <cstdint>

#define NODES 100000
#define EDGES 1600000
#define HCAT  64
#define SCB   391          // scan blocks: ceil(100000/256)

// ---------------- static scratch (no runtime allocation allowed) ------------
__device__ float g_xlin1[(size_t)NODES * HCAT];
__device__ float g_xres1[(size_t)NODES * HCAT];
__device__ float g_hbuf [(size_t)NODES * HCAT];
__device__ float g_xlin2[(size_t)NODES * HCAT];
__device__ float g_al1[NODES * 4];
__device__ float g_ar1[NODES * 4];
__device__ float g_al2[NODES];
__device__ float g_ar2[NODES];
__device__ int   g_deg [NODES];          // zero at load; scanA re-zeroes each call
__device__ int   g_offs[NODES + 1];
__device__ int   g_cur [NODES];
__device__ int   g_csr [EDGES];
__device__ int   g_bsum[SCB + 1];
__device__ int   g_boff[SCB + 1];

// ---------------- packed f32x2 + async-copy helpers ---------------------------
typedef unsigned long long ull;

__device__ __forceinline__ ull fma2(ull a, ull b, ull c) {
    ull d;
    asm("fma.rn.f32x2 %0, %1, %2, %3;" : "=l"(d) : "l"(a), "l"(b), "l"(c));
    return d;
}
__device__ __forceinline__ ull pack2(float x) {
    ull r;
    asm("mov.b64 %0, {%1, %1};" : "=l"(r) : "f"(x));
    return r;
}
__device__ __forceinline__ float2 unpack2(ull v) {
    float2 r;
    asm("mov.b64 {%0, %1}, %2;" : "=f"(r.x), "=f"(r.y) : "l"(v));
    return r;
}
__device__ __forceinline__ void cp16(unsigned int smem_addr, const void* gptr) {
    asm volatile("cp.async.ca.shared.global [%0], [%1], 16;"
                 :: "r"(smem_addr), "l"(gptr));
}
__device__ __forceinline__ void cp_commit() { asm volatile("cp.async.commit_group;"); }
__device__ __forceinline__ void cp_wait0()  { asm volatile("cp.async.wait_group 0;"); }

// ---------------- CSR build --------------------------------------------------
__global__ void hist_kernel(const int* __restrict__ dst, int* __restrict__ deg) {
    int i = blockIdx.x * blockDim.x + threadIdx.x;
    if (i < EDGES) atomicAdd(&deg[dst[i]], 1);
}

// Phase A: per-block exclusive scan of deg; zero deg; emit block sums.
__global__ void __launch_bounds__(256)
scanA_kernel(int* __restrict__ deg, int* __restrict__ offs, int* __restrict__ bsum) {
    __shared__ int sh[256];
    int t = threadIdx.x;
    int i = blockIdx.x * 256 + t;
    int d = (i < NODES) ? deg[i] : 0;
    if (i < NODES) deg[i] = 0;          // restore load-time invariant
    sh[t] = d;
    __syncthreads();
#pragma unroll
    for (int off = 1; off < 256; off <<= 1) {
        int v = (t >= off) ? sh[t - off] : 0;
        __syncthreads();
        sh[t] += v;
        __syncthreads();
    }
    if (i < NODES) offs[i] = sh[t] - d;           // block-local exclusive
    if (t == 255) bsum[blockIdx.x] = sh[255];     // block total
}

// Phase B: single-block scan of SCB block sums -> exclusive block offsets.
__global__ void __launch_bounds__(512)
scanB_kernel(const int* __restrict__ bsum, int* __restrict__ boff,
             int* __restrict__ offs) {
    __shared__ int sh[512];
    int t = threadIdx.x;
    int v = (t < SCB) ? bsum[t] : 0;
    sh[t] = v;
    __syncthreads();
#pragma unroll
    for (int off = 1; off < 512; off <<= 1) {
        int u = (t >= off) ? sh[t - off] : 0;
        __syncthreads();
        sh[t] += u;
        __syncthreads();
    }
    if (t < SCB) boff[t] = sh[t] - v;             // exclusive
    if (t == SCB - 1) offs[NODES] = sh[t];        // grand total (== EDGES)
}

// Phase C: add block offsets; materialize cur.
__global__ void __launch_bounds__(256)
scanC_kernel(int* __restrict__ offs, int* __restrict__ cur,
             const int* __restrict__ boff) {
    int i = blockIdx.x * 256 + threadIdx.x;
    if (i < NODES) {
        int o = offs[i] + boff[blockIdx.x];
        offs[i] = o;
        cur[i]  = o;
    }
}

__global__ void scatter_kernel(const int* __restrict__ src, const int* __restrict__ dst,
                               int* __restrict__ cur, int* __restrict__ csr) {
    int i = blockIdx.x * blockDim.x + threadIdx.x;
    if (i < EDGES) {
        int p = atomicAdd(&cur[dst[i]], 1);
        csr[p] = src[i];
    }
}

// ---------------- fused layer-1 GEMM: X@[W1|Wres], double-buffered -----------
__global__ void __launch_bounds__(256)
gemm1_kernel(const float* __restrict__ X, const float* __restrict__ W1,
             const float* __restrict__ Wres, const float* __restrict__ attl,
             const float* __restrict__ attr,
             float* __restrict__ xlin, float* __restrict__ xres,
             float* __restrict__ al, float* __restrict__ ar) {
    __shared__ float xs[2][32 * 68];    // [buf][k][row], stride 68
    __shared__ float ws[2][32 * 128];   // [buf][k][col 0:64=W1 | 64:128=Wres]
    const int tid  = threadIdx.x;
    const int cg   = tid & 15;
    const int rg   = tid >> 4;
    const int row0 = blockIdx.x * 64;

    const int lrow0 = (tid * 4) >> 5,          lkk0 = (tid * 4) & 31;
    const int lrow1 = (tid * 4 + 1024) >> 5,   lkk1 = (tid * 4 + 1024) & 31;
    const int gr0 = row0 + lrow0, gr1 = row0 + lrow1;
    const float* xp0 = X + (size_t)gr0 * 128 + lkk0;
    const float* xp1 = X + (size_t)gr1 * 128 + lkk1;

    ull accA[4][2], accB[4][2];
#pragma unroll
    for (int r = 0; r < 4; r++) {
        accA[r][0] = accA[r][1] = 0ull;
        accB[r][0] = accB[r][1] = 0ull;
    }

    auto issueW = [&](int k0, int buf) {
#pragma unroll
        for (int i = 0; i < 4; i++) {
            int flat = tid * 4 + i * 1024;
            int k    = flat >> 7;
            int c    = flat & 127;
            const float* src = (c < 64)
                ? (W1   + (size_t)(k0 + k) * 64 + c)
                : (Wres + (size_t)(k0 + k) * 64 + (c - 64));
            cp16((unsigned int)__cvta_generic_to_shared(&ws[buf][k * 128 + c]), src);
        }
        cp_commit();
    };
    auto loadX = [&](int k0, float4& v0, float4& v1) {
        v0 = make_float4(0.f, 0.f, 0.f, 0.f);
        v1 = make_float4(0.f, 0.f, 0.f, 0.f);
        if (gr0 < NODES) v0 = *(const float4*)(xp0 + k0);
        if (gr1 < NODES) v1 = *(const float4*)(xp1 + k0);
    };
    auto storeX = [&](int buf, const float4& v0, const float4& v1) {
        xs[buf][(lkk0 + 0) * 68 + lrow0] = v0.x;
        xs[buf][(lkk0 + 1) * 68 + lrow0] = v0.y;
        xs[buf][(lkk0 + 2) * 68 + lrow0] = v0.z;
        xs[buf][(lkk0 + 3) * 68 + lrow0] = v0.w;
        xs[buf][(lkk1 + 0) * 68 + lrow1] = v1.x;
        xs[buf][(lkk1 + 1) * 68 + lrow1] = v1.y;
        xs[buf][(lkk1 + 2) * 68 + lrow1] = v1.z;
        xs[buf][(lkk1 + 3) * 68 + lrow1] = v1.w;
    };

    {
        float4 v0, v1;
        loadX(0, v0, v1);
        issueW(0, 0);
        storeX(0, v0, v1);
        cp_wait0();
    }
    __syncthreads();

    int buf = 0;
    for (int k0 = 0; k0 < 128; k0 += 32) {
        const int nk = k0 + 32;
        float4 v0, v1;
        if (nk < 128) {
            loadX(nk, v0, v1);
            issueW(nk, buf ^ 1);
        }
        const float* xb = xs[buf];
        const float* wb = ws[buf];
#pragma unroll 8
        for (int k = 0; k < 32; k++) {
            float4 xv = *(const float4*)(&xb[k * 68 + rg * 4]);
            const float* wrow = &wb[k * 128];
            ulonglong2 wA = *(const ulonglong2*)(wrow + cg * 4);
            ulonglong2 wB = *(const ulonglong2*)(wrow + 64 + cg * 4);
            ull px0 = pack2(xv.x), px1 = pack2(xv.y);
            ull px2 = pack2(xv.z), px3 = pack2(xv.w);
            accA[0][0] = fma2(px0, wA.x, accA[0][0]);
            accA[0][1] = fma2(px0, wA.y, accA[0][1]);
            accB[0][0] = fma2(px0, wB.x, accB[0][0]);
            accB[0][1] = fma2(px0, wB.y, accB[0][1]);
            accA[1][0] = fma2(px1, wA.x, accA[1][0]);
            accA[1][1] = fma2(px1, wA.y, accA[1][1]);
            accB[1][0] = fma2(px1, wB.x, accB[1][0]);
            accB[1][1] = fma2(px1, wB.y, accB[1][1]);
            accA[2][0] = fma2(px2, wA.x, accA[2][0]);
            accA[2][1] = fma2(px2, wA.y, accA[2][1]);
            accB[2][0] = fma2(px2, wB.x, accB[2][0]);
            accB[2][1] = fma2(px2, wB.y, accB[2][1]);
            accA[3][0] = fma2(px3, wA.x, accA[3][0]);
            accA[3][1] = fma2(px3, wA.y, accA[3][1]);
            accB[3][0] = fma2(px3, wB.x, accB[3][0]);
            accB[3][1] = fma2(px3, wB.y, accB[3][1]);
        }
        if (nk < 128) {
            storeX(buf ^ 1, v0, v1);
            cp_wait0();
            __syncthreads();
            buf ^= 1;
        }
    }

    float4 la = *(const float4*)(attl + cg * 4);
    float4 ra = *(const float4*)(attr + cg * 4);
    const int h = cg >> 2;

#pragma unroll
    for (int r = 0; r < 4; r++) {
        int gr = row0 + rg * 4 + r;
        float2 a0 = unpack2(accA[r][0]), a1 = unpack2(accA[r][1]);
        float2 b0 = unpack2(accB[r][0]), b1 = unpack2(accB[r][1]);
        float4 fa = make_float4(a0.x, a0.y, a1.x, a1.y);
        float4 fb = make_float4(b0.x, b0.y, b1.x, b1.y);
        if (gr < NODES) {
            *(float4*)(xlin + (size_t)gr * 64 + cg * 4) = fa;
            *(float4*)(xres + (size_t)gr * 64 + cg * 4) = fb;
        }
        float pl = fa.x * la.x + fa.y * la.y + fa.z * la.z + fa.w * la.w;
        float pr = fa.x * ra.x + fa.y * ra.y + fa.z * ra.z + fa.w * ra.w;
        pl += __shfl_xor_sync(0xffffffffu, pl, 1);
        pl += __shfl_xor_sync(0xffffffffu, pl, 2);
        pr += __shfl_xor_sync(0xffffffffu, pr, 1);
        pr += __shfl_xor_sync(0xffffffffu, pr, 2);
        if ((cg & 3) == 0 && gr < NODES) {
            al[(size_t)gr * 4 + h] = pl;
            ar[(size_t)gr * 4 + h] = pr;
        }
    }
}

// ---------------- layer-2 GEMM: H@W2 (64x64), double-buffered ----------------
__global__ void __launch_bounds__(256)
gemm2_kernel(const float* __restrict__ X, const float* __restrict__ W,
             const float* __restrict__ attl, const float* __restrict__ attr,
             float* __restrict__ xlin, float* __restrict__ al,
             float* __restrict__ ar) {
    __shared__ float xs[2][32 * 68];
    __shared__ float ws[2][32 * 64];
    const int tid  = threadIdx.x;
    const int cg   = tid & 15;
    const int rg   = tid >> 4;
    const int row0 = blockIdx.x * 64;

    const int lrow0 = (tid * 4) >> 5,          lkk0 = (tid * 4) & 31;
    const int lrow1 = (tid * 4 + 1024) >> 5,   lkk1 = (tid * 4 + 1024) & 31;
    const int gr0 = row0 + lrow0, gr1 = row0 + lrow1;
    const float* xp0 = X + (size_t)gr0 * 64 + lkk0;
    const float* xp1 = X + (size_t)gr1 * 64 + lkk1;

    ull acc[4][2];
#pragma unroll
    for (int r = 0; r < 4; r++) acc[r][0] = acc[r][1] = 0ull;

    auto issueW = [&](int k0, int buf) {
#pragma unroll
        for (int i = 0; i < 2; i++) {
            int flat = tid * 4 + i * 1024;
            int k    = flat >> 6;
            int c    = flat & 63;
            cp16((unsigned int)__cvta_generic_to_shared(&ws[buf][k * 64 + c]),
                 W + (size_t)(k0 + k) * 64 + c);
        }
        cp_commit();
    };
    auto loadX = [&](int k0, float4& v0, float4& v1) {
        v0 = make_float4(0.f, 0.f, 0.f, 0.f);
        v1 = make_float4(0.f, 0.f, 0.f, 0.f);
        if (gr0 < NODES) v0 = *(const float4*)(xp0 + k0);
        if (gr1 < NODES) v1 = *(const float4*)(xp1 + k0);
    };
    auto storeX = [&](int buf, const float4& v0, const float4& v1) {
        xs[buf][(lkk0 + 0) * 68 + lrow0] = v0.x;
        xs[buf][(lkk0 + 1) * 68 + lrow0] = v0.y;
        xs[buf][(lkk0 + 2) * 68 + lrow0] = v0.z;
        xs[buf][(lkk0 + 3) * 68 + lrow0] = v0.w;
        xs[buf][(lkk1 + 0) * 68 + lrow1] = v1.x;
        xs[buf][(lkk1 + 1) * 68 + lrow1] = v1.y;
        xs[buf][(lkk1 + 2) * 68 + lrow1] = v1.z;
        xs[buf][(lkk1 + 3) * 68 + lrow1] = v1.w;
    };

    {
        float4 v0, v1;
        loadX(0, v0, v1);
        issueW(0, 0);
        storeX(0, v0, v1);
        cp_wait0();
    }
    __syncthreads();

    int buf = 0;
    for (int k0 = 0; k0 < 64; k0 += 32) {
        const int nk = k0 + 32;
        float4 v0, v1;
        if (nk < 64) {
            loadX(nk, v0, v1);
            issueW(nk, buf ^ 1);
        }
        const float* xb = xs[buf];
        const float* wb = ws[buf];
#pragma unroll 8
        for (int k = 0; k < 32; k++) {
            float4 xv = *(const float4*)(&xb[k * 68 + rg * 4]);
            const float* wrow = &wb[k * 64];
            ulonglong2 w01 = *(const ulonglong2*)(wrow + cg * 4);
            ull px0 = pack2(xv.x), px1 = pack2(xv.y);
            ull px2 = pack2(xv.z), px3 = pack2(xv.w);
            acc[0][0] = fma2(px0, w01.x, acc[0][0]);
            acc[0][1] = fma2(px0, w01.y, acc[0][1]);
            acc[1][0] = fma2(px1, w01.x, acc[1][0]);
            acc[1][1] = fma2(px1, w01.y, acc[1][1]);
            acc[2][0] = fma2(px2, w01.x, acc[2][0]);
            acc[2][1] = fma2(px2, w01.y, acc[2][1]);
            acc[3][0] = fma2(px3, w01.x, acc[3][0]);
            acc[3][1] = fma2(px3, w01.y, acc[3][1]);
        }
        if (nk < 64) {
            storeX(buf ^ 1, v0, v1);
            cp_wait0();
            __syncthreads();
            buf ^= 1;
        }
    }

    float4 la = *(const float4*)(attl + cg * 4);
    float4 ra = *(const float4*)(attr + cg * 4);

#pragma unroll
    for (int r = 0; r < 4; r++) {
        int gr = row0 + rg * 4 + r;
        float2 a0 = unpack2(acc[r][0]), a1 = unpack2(acc[r][1]);
        float4 fa = make_float4(a0.x, a0.y, a1.x, a1.y);
        if (gr < NODES)
            *(float4*)(xlin + (size_t)gr * 64 + cg * 4) = fa;
        float pl = fa.x * la.x + fa.y * la.y + fa.z * la.z + fa.w * la.w;
        float pr = fa.x * ra.x + fa.y * ra.y + fa.z * ra.z + fa.w * ra.w;
#pragma unroll
        for (int o = 1; o <= 8; o <<= 1) {
            pl += __shfl_xor_sync(0xffffffffu, pl, o);
            pr += __shfl_xor_sync(0xffffffffu, pr, o);
        }
        if (cg == 0 && gr < NODES) {
            al[gr] = pl;
            ar[gr] = pr;
        }
    }
}

// ---------------- fused softmax-attention aggregation (no max pass) ----------
template <int H, int C, bool ELU>
__global__ void __launch_bounds__(256)
agg_kernel(const int* __restrict__ offs, const int* __restrict__ csr,
           const float* __restrict__ xlin, const float* __restrict__ al,
           const float* __restrict__ ar, const float* __restrict__ xres,
           const float* __restrict__ bias, float* __restrict__ out) {
    int w = (blockIdx.x * blockDim.x + threadIdx.x) >> 5;
    if (w >= NODES) return;
    const int lane = threadIdx.x & 31;
    const int hl   = lane & 15;
    const int half = lane >> 4;
    const int myh  = (4 * hl) / C;
    const int o0 = offs[w];
    const int o1 = offs[w + 1];

    const float ar_my = ar[w * H + myh];
    const float4* __restrict__ xl4 = (const float4*)xlin + hl;
    const float*  __restrict__ alh = al + myh;

    float4 acc = make_float4(0.f, 0.f, 0.f, 0.f);
    float  ssum = 0.f;
    for (int i = o0 + half; i < o1; i += 2) {
        int s = csr[i];
        float v = alh[s * H] + ar_my;
        v = v > 0.f ? v : 0.2f * v;
        float e = __expf(v);
        ssum += e;
        float4 xv = xl4[s * 16];
        acc.x += e * xv.x; acc.y += e * xv.y; acc.z += e * xv.z; acc.w += e * xv.w;
    }
    acc.x += __shfl_xor_sync(0xffffffffu, acc.x, 16);
    acc.y += __shfl_xor_sync(0xffffffffu, acc.y, 16);
    acc.z += __shfl_xor_sync(0xffffffffu, acc.z, 16);
    acc.w += __shfl_xor_sync(0xffffffffu, acc.w, 16);
    ssum  += __shfl_xor_sync(0xffffffffu, ssum, 16);

    if (half == 0) {
        float inv = 1.f / (ssum + 1e-16f);
        float4 rv = ((const float4*)xres)[w * 16 + hl];
        float4 bv = ((const float4*)bias)[hl];
        float4 r;
        r.x = acc.x * inv + rv.x + bv.x;
        r.y = acc.y * inv + rv.y + bv.y;
        r.z = acc.z * inv + rv.z + bv.z;
        r.w = acc.w * inv + rv.w + bv.w;
        if (ELU) {
            r.x = r.x > 0.f ? r.x : __expf(r.x) - 1.f;
            r.y = r.y > 0.f ? r.y : __expf(r.y) - 1.f;
            r.z = r.z > 0.f ? r.z : __expf(r.z) - 1.f;
            r.w = r.w > 0.f ? r.w : __expf(r.w) - 1.f;
        }
        ((float4*)out)[w * 16 + hl] = r;
    }
}

// ---------------- launch: serial single-stream (fork-join regressed) ---------
extern "C" void kernel_launch(void* const* d_in, const int* in_sizes, int n_in,
                              void* d_out, int out_size) {
    const float* x     = (const float*)d_in[0];
    const int*   ei    = (const int*)d_in[1];
    const float* W1    = (const float*)d_in[2];
    const float* attl1 = (const float*)d_in[3];
    const float* attr1 = (const float*)d_in[4];
    const float* resW1 = (const float*)d_in[5];
    const float* b1    = (const float*)d_in[6];
    const float* W2    = (const float*)d_in[7];
    const float* attl2 = (const float*)d_in[8];
    const float* attr2 = (const float*)d_in[9];
    const float* b2    = (const float*)d_in[10];
    float* out = (float*)d_out;
    const int* src = ei;
    const int* dst = ei + EDGES;

    float *xlin1, *xres1, *hbuf, *xlin2, *al1, *ar1, *al2, *ar2;
    int *deg, *offs, *cur, *csr, *bsum, *boff;
    cudaGetSymbolAddress((void**)&xlin1, g_xlin1);
    cudaGetSymbolAddress((void**)&xres1, g_xres1);
    cudaGetSymbolAddress((void**)&hbuf,  g_hbuf);
    cudaGetSymbolAddress((void**)&xlin2, g_xlin2);
    cudaGetSymbolAddress((void**)&al1,   g_al1);
    cudaGetSymbolAddress((void**)&ar1,   g_ar1);
    cudaGetSymbolAddress((void**)&al2,   g_al2);
    cudaGetSymbolAddress((void**)&ar2,   g_ar2);
    cudaGetSymbolAddress((void**)&deg,   g_deg);
    cudaGetSymbolAddress((void**)&offs,  g_offs);
    cudaGetSymbolAddress((void**)&cur,   g_cur);
    cudaGetSymbolAddress((void**)&csr,   g_csr);
    cudaGetSymbolAddress((void**)&bsum,  g_bsum);
    cudaGetSymbolAddress((void**)&boff,  g_boff);

    const int TB = 256;
    const int GB = (NODES + 63) / 64;
    const int WG = (NODES * 32 + TB - 1) / TB;   // warp per node
    const int HB = (EDGES + TB - 1) / TB;

    hist_kernel<<<HB, TB>>>(dst, deg);
    scanA_kernel<<<SCB, 256>>>(deg, offs, bsum);       // zeroes deg too
    scanB_kernel<<<1, 512>>>(bsum, boff, offs);
    gemm1_kernel<<<GB, 256>>>(x, W1, resW1, attl1, attr1,
                              xlin1, xres1, al1, ar1);  // ncu slot 4
    scanC_kernel<<<SCB, 256>>>(offs, cur, boff);
    scatter_kernel<<<HB, TB>>>(src, dst, cur, csr);

    agg_kernel<4, 16, true><<<WG, TB>>>(offs, csr, xlin1, al1, ar1, xres1, b1, hbuf);
    gemm2_kernel<<<GB, 256>>>(hbuf, W2, attl2, attr2, xlin2, al2, ar2);
    agg_kernel<1, 64, false><<<WG, TB>>>(offs, csr, xlin2, al2, ar2, xlin2, b2, out);
}